// round 1
// baseline (speedup 1.0000x reference)
#include <cuda_runtime.h>
#include <math.h>

#define NN 100000
#define HH 64

// ---------------- scratch (device globals: no allocation allowed) ----------
__device__ float g_y[(size_t)NN * HH];     // GEMM output (pre-aggregation)
__device__ float g_agg[(size_t)NN * HH];   // aggregation target
__device__ float g_hpos[(size_t)NN * HH];
__device__ float g_hneg[(size_t)NN * HH];
__device__ float g_zpos[(size_t)NN * HH];
__device__ float g_norms[4 * NN];          // c_src_pos | c_dst_pos | c_src_neg | c_dst_neg

// ---------------- vectorized global reduction ------------------------------
__device__ __forceinline__ void red_add_v4(float* addr, float4 v) {
    asm volatile("red.global.add.v4.f32 [%0], {%1,%2,%3,%4};"
                 :: "l"(addr), "f"(v.x), "f"(v.y), "f"(v.z), "f"(v.w)
                 : "memory");
}

// ---------------- kernels ---------------------------------------------------
__global__ void zero_kernel(float4* __restrict__ p, int n4) {
    int t = blockIdx.x * blockDim.x + threadIdx.x;
    if (t < n4) p[t] = make_float4(0.f, 0.f, 0.f, 0.f);
}

__global__ void deg_kernel(const int* __restrict__ idx, float* __restrict__ deg, int n) {
    int t = blockIdx.x * blockDim.x + threadIdx.x;
    if (t < n) atomicAdd(deg + idx[t], 1.0f);
}

__global__ void norm_kernel(float* __restrict__ deg, int n) {
    int t = blockIdx.x * blockDim.x + threadIdx.x;
    if (t < n) {
        float d = deg[t];
        deg[t] = (d > 0.f) ? rsqrtf(d) : 0.f;
    }
}

// Y[i,:] = (X[i,:] * c[i]) @ W   (X: n x 64, W: 64 x 64 row-major)
// block = 256 threads, 32 rows per block. Thread computes 8 outputs.
__global__ void gemm_scale(const float* __restrict__ X, const float* __restrict__ c,
                           const float* __restrict__ W, float* __restrict__ Y, int n) {
    __shared__ float Ws[64 * 64];
    __shared__ float Xs[32 * 65];   // padded stride to kill bank conflicts

    int tid = threadIdx.x;
    int row0 = blockIdx.x * 32;

    #pragma unroll
    for (int i = tid; i < 64 * 64; i += 256) Ws[i] = W[i];

    for (int i = tid; i < 32 * 64; i += 256) {
        int r = i >> 6, k = i & 63;
        int gr = row0 + r;
        float v = 0.f;
        if (gr < n) v = X[(size_t)gr * 64 + k] * c[gr];
        Xs[r * 65 + k] = v;
    }
    __syncthreads();

    int r  = tid >> 3;            // 0..31
    int cg = (tid & 7) * 8;       // col base (0,8,...,56)
    float acc[8];
    #pragma unroll
    for (int j = 0; j < 8; j++) acc[j] = 0.f;

    #pragma unroll
    for (int k = 0; k < 64; k++) {
        float xv = Xs[r * 65 + k];
        float4 w0 = *(const float4*)&Ws[k * 64 + cg];
        float4 w1 = *(const float4*)&Ws[k * 64 + cg + 4];
        acc[0] += xv * w0.x; acc[1] += xv * w0.y;
        acc[2] += xv * w0.z; acc[3] += xv * w0.w;
        acc[4] += xv * w1.x; acc[5] += xv * w1.y;
        acc[6] += xv * w1.z; acc[7] += xv * w1.w;
    }

    int gr = row0 + r;
    if (gr < n) {
        *(float4*)&Y[(size_t)gr * 64 + cg]     = make_float4(acc[0], acc[1], acc[2], acc[3]);
        *(float4*)&Y[(size_t)gr * 64 + cg + 4] = make_float4(acc[4], acc[5], acc[6], acc[7]);
    }
}

// agg[dst[e],:] += y[src[e],:]   — 16 threads per edge, float4 each
__global__ void aggregate(const float* __restrict__ y, const int* __restrict__ src,
                          const int* __restrict__ dst, float* __restrict__ agg, int nE) {
    int t = blockIdx.x * blockDim.x + threadIdx.x;
    int e = t >> 4;
    if (e >= nE) return;
    int cb = (t & 15) << 2;
    int s = __ldg(src + e);
    int d = __ldg(dst + e);
    float4 v = *(const float4*)(y + (size_t)s * 64 + cb);
    red_add_v4(agg + (size_t)d * 64 + cb, v);
}

// out[i,j] = relu(c[i]*agg[i,j] + b[j])
__global__ void epilogue_relu(const float* __restrict__ agg, const float* __restrict__ c,
                              const float* __restrict__ b, float* __restrict__ out, int n) {
    int t = blockIdx.x * blockDim.x + threadIdx.x;
    if (t >= n * 16) return;
    int i  = t >> 4;
    int j4 = (t & 15) << 2;
    float cv = c[i];
    float4 a = *(const float4*)(agg + (size_t)i * 64 + j4);
    float4 r;
    r.x = fmaxf(cv * a.x + b[j4 + 0], 0.f);
    r.y = fmaxf(cv * a.y + b[j4 + 1], 0.f);
    r.z = fmaxf(cv * a.z + b[j4 + 2], 0.f);
    r.w = fmaxf(cv * a.w + b[j4 + 3], 0.f);
    *(float4*)(out + (size_t)i * 64 + j4) = r;
}

// z[i,j] = zpos[i,j] - relu(c[i]*agg[i,j] + b[j])
__global__ void epilogue_combine(const float* __restrict__ agg, const float* __restrict__ c,
                                 const float* __restrict__ b, const float* __restrict__ zpos,
                                 float* __restrict__ zout, int n) {
    int t = blockIdx.x * blockDim.x + threadIdx.x;
    if (t >= n * 16) return;
    int i  = t >> 4;
    int j4 = (t & 15) << 2;
    float cv = c[i];
    float4 a = *(const float4*)(agg + (size_t)i * 64 + j4);
    float4 p = *(const float4*)(zpos + (size_t)i * 64 + j4);
    float4 r;
    r.x = p.x - fmaxf(cv * a.x + b[j4 + 0], 0.f);
    r.y = p.y - fmaxf(cv * a.y + b[j4 + 1], 0.f);
    r.z = p.z - fmaxf(cv * a.z + b[j4 + 2], 0.f);
    r.w = p.w - fmaxf(cv * a.w + b[j4 + 3], 0.f);
    *(float4*)(zout + (size_t)i * 64 + j4) = r;
}

// probs[q,:] = sigmoid([z[src_q], z[dst_q]] @ Wc + bc)   — one warp per query edge
__global__ void classifier(const float* __restrict__ z, const int* __restrict__ ei,
                           const float* __restrict__ Wc, const float* __restrict__ bc,
                           float* __restrict__ out, int nQ) {
    __shared__ float Wcs[256];
    int tid = threadIdx.x;
    Wcs[tid] = Wc[tid];          // blockDim == 256, Wc is 128x2 = 256 floats
    __syncthreads();

    int warp = (blockIdx.x * blockDim.x + tid) >> 5;
    int lane = tid & 31;
    if (warp >= nQ) return;

    int node = (lane < 16) ? __ldg(ei + warp) : __ldg(ei + nQ + warp);
    int cb = (lane & 15) * 4;
    float4 v = *(const float4*)(z + (size_t)node * 64 + cb);
    int wr = lane * 4;           // lanes 0..15 -> rows 0..63 (src half), 16..31 -> 64..127 (dst half)

    float a0 = v.x * Wcs[(wr + 0) * 2] + v.y * Wcs[(wr + 1) * 2]
             + v.z * Wcs[(wr + 2) * 2] + v.w * Wcs[(wr + 3) * 2];
    float a1 = v.x * Wcs[(wr + 0) * 2 + 1] + v.y * Wcs[(wr + 1) * 2 + 1]
             + v.z * Wcs[(wr + 2) * 2 + 1] + v.w * Wcs[(wr + 3) * 2 + 1];

    #pragma unroll
    for (int o = 16; o > 0; o >>= 1) {
        a0 += __shfl_xor_sync(0xffffffffu, a0, o);
        a1 += __shfl_xor_sync(0xffffffffu, a1, o);
    }
    if (lane == 0) {
        float l0 = a0 + bc[0];
        float l1 = a1 + bc[1];
        out[(size_t)warp * 2 + 0] = 1.f / (1.f + expf(-l0));
        out[(size_t)warp * 2 + 1] = 1.f / (1.f + expf(-l1));
    }
}

// ---------------- launch ----------------------------------------------------
static inline int cdiv(long long a, int b) { return (int)((a + b - 1) / b); }

extern "C" void kernel_launch(void* const* d_in, const int* in_sizes, int n_in,
                              void* d_out, int out_size) {
    const float* x    = (const float*)d_in[0];
    const float* W0p  = (const float*)d_in[1];
    const float* b0p  = (const float*)d_in[2];
    const float* W0n  = (const float*)d_in[3];
    const float* b0n  = (const float*)d_in[4];
    const float* W1p  = (const float*)d_in[5];
    const float* b1p  = (const float*)d_in[6];
    const float* W1n  = (const float*)d_in[7];
    const float* b1n  = (const float*)d_in[8];
    const float* Wc   = (const float*)d_in[9];
    const float* bc   = (const float*)d_in[10];
    const int*   srcp = (const int*)d_in[11];
    const int*   dstp = (const int*)d_in[12];
    const int*   srcn = (const int*)d_in[13];
    const int*   dstn = (const int*)d_in[14];
    const int*   ei   = (const int*)d_in[15];

    const int n  = in_sizes[0] / HH;     // 100000
    const int nE = in_sizes[11];         // 1.6M
    const int nQ = in_sizes[15] / 2;     // 1M

    float *y, *agg, *hp, *hn, *zp, *norms;
    cudaGetSymbolAddress((void**)&y,     g_y);
    cudaGetSymbolAddress((void**)&agg,   g_agg);
    cudaGetSymbolAddress((void**)&hp,    g_hpos);
    cudaGetSymbolAddress((void**)&hn,    g_hneg);
    cudaGetSymbolAddress((void**)&zp,    g_zpos);
    cudaGetSymbolAddress((void**)&norms, g_norms);

    float* csp = norms;
    float* cdp = norms + n;
    float* csn = norms + 2 * n;
    float* cdn = norms + 3 * n;

    float* z     = (float*)d_out;                       // first n*64 floats
    float* probs = (float*)d_out + (size_t)n * HH;      // then nQ*2 floats

    // ---- degree norms (recomputed every call; deterministic up to fp atomics)
    zero_kernel<<<cdiv(n, 256), 256>>>((float4*)norms, n);  // 4n floats = n float4
    deg_kernel<<<cdiv(nE, 256), 256>>>(srcp, csp, nE);
    deg_kernel<<<cdiv(nE, 256), 256>>>(dstp, cdp, nE);
    deg_kernel<<<cdiv(nE, 256), 256>>>(srcn, csn, nE);
    deg_kernel<<<cdiv(nE, 256), 256>>>(dstn, cdn, nE);
    norm_kernel<<<cdiv(4 * n, 256), 256>>>(norms, 4 * n);

    const int gElem  = cdiv((long long)n * 16, 256);          // n*64/4 elements
    const int gGemm  = cdiv(n, 32);
    const int gAggr  = cdiv((long long)nE * 16, 256);

    // ---- conv1 pos: h_pos = relu(c_dst ⊙ Agg((x ⊙ c_src) @ W0p) + b0p)
    gemm_scale<<<gGemm, 256>>>(x, csp, W0p, y, n);
    zero_kernel<<<gElem, 256>>>((float4*)agg, n * 16);
    aggregate<<<gAggr, 256>>>(y, srcp, dstp, agg, nE);
    epilogue_relu<<<gElem, 256>>>(agg, cdp, b0p, hp, n);

    // ---- conv1 neg
    gemm_scale<<<gGemm, 256>>>(x, csn, W0n, y, n);
    zero_kernel<<<gElem, 256>>>((float4*)agg, n * 16);
    aggregate<<<gAggr, 256>>>(y, srcn, dstn, agg, nE);
    epilogue_relu<<<gElem, 256>>>(agg, cdn, b0n, hn, n);

    // ---- conv2 pos -> z_pos
    gemm_scale<<<gGemm, 256>>>(hp, csp, W1p, y, n);
    zero_kernel<<<gElem, 256>>>((float4*)agg, n * 16);
    aggregate<<<gAggr, 256>>>(y, srcp, dstp, agg, nE);
    epilogue_relu<<<gElem, 256>>>(agg, cdp, b1p, zp, n);

    // ---- conv2 neg, fused with z = z_pos - z_neg, written straight to d_out
    gemm_scale<<<gGemm, 256>>>(hn, csn, W1n, y, n);
    zero_kernel<<<gElem, 256>>>((float4*)agg, n * 16);
    aggregate<<<gAggr, 256>>>(y, srcn, dstn, agg, nE);
    epilogue_combine<<<gElem, 256>>>(agg, cdn, b1n, zp, z, n);

    // ---- edge classifier
    classifier<<<cdiv(nQ, 8), 256>>>(z, ei, Wc, bc, probs, nQ);
}

// round 2
// speedup vs baseline: 1.5046x; 1.5046x over previous
#include <cuda_runtime.h>
#include <math.h>

#define NN 100000
#define HH 64

// ---------------- scratch (device globals: no allocation allowed) ----------
__device__ float g_y[2 * (size_t)NN * HH];    // GEMM outputs, [rel][N][64]
__device__ float g_agg[2 * (size_t)NN * HH];  // aggregation targets, [rel][N][64]
__device__ float g_norms[4 * NN];             // csp | cdp | csn | cdn
__device__ float g_proj[4 * NN];              // per-node classifier projections [N][4]

// ---------------- packed fp32x2 helpers (Blackwell double-rate fp32) -------
__device__ __forceinline__ unsigned long long pack2(float a, float b) {
    unsigned long long r;
    asm("mov.b64 %0, {%1,%2};" : "=l"(r) : "f"(a), "f"(b));
    return r;
}
__device__ __forceinline__ void fma2(unsigned long long& d, unsigned long long a,
                                     unsigned long long b) {
    asm("fma.rn.f32x2 %0, %1, %2, %3;" : "=l"(d) : "l"(a), "l"(b), "l"(d));
}
__device__ __forceinline__ unsigned long long mul2(unsigned long long a,
                                                   unsigned long long b) {
    unsigned long long r;
    asm("mul.rn.f32x2 %0, %1, %2;" : "=l"(r) : "l"(a), "l"(b));
    return r;
}

__device__ __forceinline__ void red_add_v4(float* addr, float4 v) {
    asm volatile("red.global.add.v4.f32 [%0], {%1,%2,%3,%4};"
                 :: "l"(addr), "f"(v.x), "f"(v.y), "f"(v.z), "f"(v.w)
                 : "memory");
}

// ---------------- small utility kernels -------------------------------------
__global__ void zero_kernel(float4* __restrict__ p, int n4) {
    int t = blockIdx.x * blockDim.x + threadIdx.x;
    if (t < n4) p[t] = make_float4(0.f, 0.f, 0.f, 0.f);
}

// all four degree counts in one launch (blockIdx.y selects stream)
__global__ void deg4_kernel(const int* __restrict__ sp, const int* __restrict__ dp,
                            const int* __restrict__ sn, const int* __restrict__ dn,
                            float* __restrict__ norms, int n, int nE) {
    int t = blockIdx.x * blockDim.x + threadIdx.x;
    if (t >= nE) return;
    int w = blockIdx.y;
    const int* idx = (w == 0) ? sp : (w == 1) ? dp : (w == 2) ? sn : dn;
    atomicAdd(norms + (size_t)w * n + idx[t], 1.0f);
}

__global__ void norm_kernel(float* __restrict__ deg, int n) {
    int t = blockIdx.x * blockDim.x + threadIdx.x;
    if (t < n) {
        float d = deg[t];
        deg[t] = (d > 0.f) ? rsqrtf(d) : 0.f;
    }
}

// ---------------- layer-1 GEMM: Y_rel[i,:] = c_rel[i] * (X[i,:] @ W_rel) ----
// 64 rows/block, 256 threads; thread: 2 rows x 8 cols x 2 mats, FFMA2 col-pairs.
__global__ void __launch_bounds__(256)
gemm_x_dual(const float* __restrict__ X,
            const float* __restrict__ csp, const float* __restrict__ csn,
            const float* __restrict__ Wp, const float* __restrict__ Wn,
            float* __restrict__ Yp, float* __restrict__ Yn, int n) {
    __shared__ float Ws[2 * 4096];
    __shared__ float Xs[4096];
    int tid = threadIdx.x;
    int row0 = blockIdx.x * 64;

    {
        float4* d = (float4*)Ws;
        const float4* s1 = (const float4*)Wp;
        const float4* s2 = (const float4*)Wn;
        #pragma unroll
        for (int i = tid; i < 1024; i += 256) d[i] = s1[i];
        #pragma unroll
        for (int i = tid; i < 1024; i += 256) d[1024 + i] = s2[i];
    }
    {
        float4* d = (float4*)Xs;
        for (int i = tid; i < 1024; i += 256) {
            int r = i >> 4;
            int gr = row0 + r;
            d[i] = (gr < n) ? ((const float4*)X)[(size_t)gr * 16 + (i & 15)]
                            : make_float4(0.f, 0.f, 0.f, 0.f);
        }
    }
    __syncthreads();

    int r0 = (tid >> 3) * 2;
    int cg = (tid & 7) * 8;
    unsigned long long ap0[4] = {0, 0, 0, 0}, ap1[4] = {0, 0, 0, 0};
    unsigned long long an0[4] = {0, 0, 0, 0}, an1[4] = {0, 0, 0, 0};

    #pragma unroll
    for (int k = 0; k < 64; k += 4) {
        float4 xv0 = *(const float4*)&Xs[r0 * 64 + k];
        float4 xv1 = *(const float4*)&Xs[(r0 + 1) * 64 + k];
        float x0a[4] = {xv0.x, xv0.y, xv0.z, xv0.w};
        float x1a[4] = {xv1.x, xv1.y, xv1.z, xv1.w};
        #pragma unroll
        for (int kk = 0; kk < 4; kk++) {
            unsigned long long X0 = pack2(x0a[kk], x0a[kk]);
            unsigned long long X1 = pack2(x1a[kk], x1a[kk]);
            ulonglong2 wpa = *(const ulonglong2*)&Ws[(k + kk) * 64 + cg];
            ulonglong2 wpb = *(const ulonglong2*)&Ws[(k + kk) * 64 + cg + 4];
            ulonglong2 wna = *(const ulonglong2*)&Ws[4096 + (k + kk) * 64 + cg];
            ulonglong2 wnb = *(const ulonglong2*)&Ws[4096 + (k + kk) * 64 + cg + 4];
            fma2(ap0[0], X0, wpa.x); fma2(ap0[1], X0, wpa.y);
            fma2(ap0[2], X0, wpb.x); fma2(ap0[3], X0, wpb.y);
            fma2(ap1[0], X1, wpa.x); fma2(ap1[1], X1, wpa.y);
            fma2(ap1[2], X1, wpb.x); fma2(ap1[3], X1, wpb.y);
            fma2(an0[0], X0, wna.x); fma2(an0[1], X0, wna.y);
            fma2(an0[2], X0, wnb.x); fma2(an0[3], X0, wnb.y);
            fma2(an1[0], X1, wna.x); fma2(an1[1], X1, wna.y);
            fma2(an1[2], X1, wnb.x); fma2(an1[3], X1, wnb.y);
        }
    }

    #pragma unroll
    for (int rr = 0; rr < 2; rr++) {
        int gr = row0 + r0 + rr;
        if (gr >= n) continue;
        unsigned long long cp = pack2(csp[gr], csp[gr]);
        unsigned long long cn = pack2(csn[gr], csn[gr]);
        unsigned long long* Ap = rr ? ap1 : ap0;
        unsigned long long* An = rr ? an1 : an0;
        ulonglong2 o0, o1;
        o0.x = mul2(Ap[0], cp); o0.y = mul2(Ap[1], cp);
        o1.x = mul2(Ap[2], cp); o1.y = mul2(Ap[3], cp);
        *(ulonglong2*)&Yp[(size_t)gr * 64 + cg] = o0;
        *(ulonglong2*)&Yp[(size_t)gr * 64 + cg + 4] = o1;
        o0.x = mul2(An[0], cn); o0.y = mul2(An[1], cn);
        o1.x = mul2(An[2], cn); o1.y = mul2(An[3], cn);
        *(ulonglong2*)&Yn[(size_t)gr * 64 + cg] = o0;
        *(ulonglong2*)&Yn[(size_t)gr * 64 + cg + 4] = o1;
    }
}

// ---------------- layer-2 GEMM with fused layer-1 epilogue ------------------
// X_eff[i,k] = relu(c_dst[i]*agg[i,k] + b0[k]);  Y[i,:] = c_src[i]*(X_eff[i,:] @ W1)
__global__ void __launch_bounds__(256)
gemm_l2(const float* __restrict__ agg, const float* __restrict__ norms,
        const float* __restrict__ b0p, const float* __restrict__ b0n,
        const float* __restrict__ W1p, const float* __restrict__ W1n,
        float* __restrict__ Y, int n) {
    int rel = blockIdx.y;
    const float* A  = agg + (size_t)rel * n * 64;
    const float* cd = norms + n + 2 * (size_t)rel * n;
    const float* cs = norms + 2 * (size_t)rel * n;
    const float* b0 = rel ? b0n : b0p;
    const float* W  = rel ? W1n : W1p;
    float* Yo = Y + (size_t)rel * n * 64;

    __shared__ float Ws[4096];
    __shared__ float Xs[4096];
    __shared__ float bs[64];
    int tid = threadIdx.x;
    int row0 = blockIdx.x * 64;

    if (tid < 64) bs[tid] = b0[tid];
    #pragma unroll
    for (int i = tid; i < 1024; i += 256) ((float4*)Ws)[i] = ((const float4*)W)[i];
    __syncthreads();

    for (int i = tid; i < 1024; i += 256) {
        int r = i >> 4;
        int gr = row0 + r;
        int k4 = (i & 15) * 4;
        float4 v = make_float4(0.f, 0.f, 0.f, 0.f);
        if (gr < n) {
            float c = cd[gr];
            float4 a = ((const float4*)A)[(size_t)gr * 16 + (i & 15)];
            v.x = fmaxf(c * a.x + bs[k4 + 0], 0.f);
            v.y = fmaxf(c * a.y + bs[k4 + 1], 0.f);
            v.z = fmaxf(c * a.z + bs[k4 + 2], 0.f);
            v.w = fmaxf(c * a.w + bs[k4 + 3], 0.f);
        }
        ((float4*)Xs)[i] = v;
    }
    __syncthreads();

    int r0 = (tid >> 3) * 2;
    int cg = (tid & 7) * 8;
    unsigned long long a0[4] = {0, 0, 0, 0}, a1[4] = {0, 0, 0, 0};

    #pragma unroll
    for (int k = 0; k < 64; k += 4) {
        float4 xv0 = *(const float4*)&Xs[r0 * 64 + k];
        float4 xv1 = *(const float4*)&Xs[(r0 + 1) * 64 + k];
        float x0a[4] = {xv0.x, xv0.y, xv0.z, xv0.w};
        float x1a[4] = {xv1.x, xv1.y, xv1.z, xv1.w};
        #pragma unroll
        for (int kk = 0; kk < 4; kk++) {
            unsigned long long X0 = pack2(x0a[kk], x0a[kk]);
            unsigned long long X1 = pack2(x1a[kk], x1a[kk]);
            ulonglong2 wa = *(const ulonglong2*)&Ws[(k + kk) * 64 + cg];
            ulonglong2 wb = *(const ulonglong2*)&Ws[(k + kk) * 64 + cg + 4];
            fma2(a0[0], X0, wa.x); fma2(a0[1], X0, wa.y);
            fma2(a0[2], X0, wb.x); fma2(a0[3], X0, wb.y);
            fma2(a1[0], X1, wa.x); fma2(a1[1], X1, wa.y);
            fma2(a1[2], X1, wb.x); fma2(a1[3], X1, wb.y);
        }
    }

    #pragma unroll
    for (int rr = 0; rr < 2; rr++) {
        int gr = row0 + r0 + rr;
        if (gr >= n) continue;
        unsigned long long c2 = pack2(cs[gr], cs[gr]);
        unsigned long long* Ar = rr ? a1 : a0;
        ulonglong2 o0, o1;
        o0.x = mul2(Ar[0], c2); o0.y = mul2(Ar[1], c2);
        o1.x = mul2(Ar[2], c2); o1.y = mul2(Ar[3], c2);
        *(ulonglong2*)&Yo[(size_t)gr * 64 + cg] = o0;
        *(ulonglong2*)&Yo[(size_t)gr * 64 + cg + 4] = o1;
    }
}

// ---------------- aggregation (both relations, blockIdx.y selects) ----------
__global__ void aggregate(const float* __restrict__ y,
                          const int* __restrict__ srcp, const int* __restrict__ dstp,
                          const int* __restrict__ srcn, const int* __restrict__ dstn,
                          float* __restrict__ agg, int n, int nE) {
    int rel = blockIdx.y;
    const int* src = rel ? srcn : srcp;
    const int* dst = rel ? dstn : dstp;
    const float* Y = y + (size_t)rel * n * 64;
    float* A = agg + (size_t)rel * n * 64;

    int t = blockIdx.x * blockDim.x + threadIdx.x;
    int e = t >> 4;
    if (e >= nE) return;
    int cb = (t & 15) << 2;
    int s = __ldg(src + e);
    int d = __ldg(dst + e);
    float4 v = *(const float4*)(Y + (size_t)s * 64 + cb);
    red_add_v4(A + (size_t)d * 64 + cb, v);
}

// ---------------- final combine: z = relu(pos) - relu(neg), into d_out ------
__global__ void combine(const float* __restrict__ agg, const float* __restrict__ norms,
                        const float* __restrict__ b1p, const float* __restrict__ b1n,
                        float* __restrict__ z, int n) {
    int t = blockIdx.x * blockDim.x + threadIdx.x;
    if (t >= n * 16) return;
    int i = t >> 4;
    int j4 = (t & 15) << 2;
    float cp = norms[n + i];
    float cn = norms[3 * (size_t)n + i];
    float4 ap = ((const float4*)agg)[t];
    float4 an = ((const float4*)(agg + (size_t)n * 64))[t];
    float4 r;
    r.x = fmaxf(cp * ap.x + b1p[j4 + 0], 0.f) - fmaxf(cn * an.x + b1n[j4 + 0], 0.f);
    r.y = fmaxf(cp * ap.y + b1p[j4 + 1], 0.f) - fmaxf(cn * an.y + b1n[j4 + 1], 0.f);
    r.z = fmaxf(cp * ap.z + b1p[j4 + 2], 0.f) - fmaxf(cn * an.z + b1n[j4 + 2], 0.f);
    r.w = fmaxf(cp * ap.w + b1p[j4 + 3], 0.f) - fmaxf(cn * an.w + b1n[j4 + 3], 0.f);
    ((float4*)z)[t] = r;
}

// ---------------- per-node classifier projections: p[i] = z[i] @ Wc halves --
__global__ void proj_kernel(const float* __restrict__ z, const float* __restrict__ Wc,
                            float* __restrict__ p, int n) {
    __shared__ float Wcs[256];
    int tid = threadIdx.x;
    Wcs[tid] = Wc[tid];
    __syncthreads();

    int warp = (blockIdx.x * 256 + tid) >> 5;
    int lane = tid & 31;
    if (warp >= n) return;

    float z0 = z[(size_t)warp * 64 + lane];
    float z1 = z[(size_t)warp * 64 + 32 + lane];
    float s0 = z0 * Wcs[lane * 2 + 0] + z1 * Wcs[(lane + 32) * 2 + 0];
    float s1 = z0 * Wcs[lane * 2 + 1] + z1 * Wcs[(lane + 32) * 2 + 1];
    float d0 = z0 * Wcs[128 + lane * 2 + 0] + z1 * Wcs[128 + (lane + 32) * 2 + 0];
    float d1 = z0 * Wcs[128 + lane * 2 + 1] + z1 * Wcs[128 + (lane + 32) * 2 + 1];
    #pragma unroll
    for (int o = 16; o > 0; o >>= 1) {
        s0 += __shfl_xor_sync(0xffffffffu, s0, o);
        s1 += __shfl_xor_sync(0xffffffffu, s1, o);
        d0 += __shfl_xor_sync(0xffffffffu, d0, o);
        d1 += __shfl_xor_sync(0xffffffffu, d1, o);
    }
    if (lane == 0) ((float4*)p)[warp] = make_float4(s0, s1, d0, d1);
}

// ---------------- classifier: 16B per query instead of 512B -----------------
__global__ void cls_kernel(const float* __restrict__ p, const int* __restrict__ ei,
                           const float* __restrict__ bc, float* __restrict__ out, int nQ) {
    int q = blockIdx.x * blockDim.x + threadIdx.x;
    if (q >= nQ) return;
    int s = __ldg(ei + q);
    int d = __ldg(ei + nQ + q);
    float4 ps = ((const float4*)p)[s];
    float4 pd = ((const float4*)p)[d];
    float l0 = ps.x + pd.z + bc[0];
    float l1 = ps.y + pd.w + bc[1];
    float2 o;
    o.x = 1.f / (1.f + expf(-l0));
    o.y = 1.f / (1.f + expf(-l1));
    ((float2*)out)[q] = o;
}

// ---------------- launch ----------------------------------------------------
static inline int cdiv(long long a, int b) { return (int)((a + b - 1) / b); }

extern "C" void kernel_launch(void* const* d_in, const int* in_sizes, int n_in,
                              void* d_out, int out_size) {
    const float* x    = (const float*)d_in[0];
    const float* W0p  = (const float*)d_in[1];
    const float* b0p  = (const float*)d_in[2];
    const float* W0n  = (const float*)d_in[3];
    const float* b0n  = (const float*)d_in[4];
    const float* W1p  = (const float*)d_in[5];
    const float* b1p  = (const float*)d_in[6];
    const float* W1n  = (const float*)d_in[7];
    const float* b1n  = (const float*)d_in[8];
    const float* Wc   = (const float*)d_in[9];
    const float* bc   = (const float*)d_in[10];
    const int*   srcp = (const int*)d_in[11];
    const int*   dstp = (const int*)d_in[12];
    const int*   srcn = (const int*)d_in[13];
    const int*   dstn = (const int*)d_in[14];
    const int*   ei   = (const int*)d_in[15];

    const int n  = in_sizes[0] / HH;   // 100000
    const int nE = in_sizes[11];       // 1.6M
    const int nQ = in_sizes[15] / 2;   // 1M

    float *y, *agg, *norms, *pbuf;
    cudaGetSymbolAddress((void**)&y,     g_y);
    cudaGetSymbolAddress((void**)&agg,   g_agg);
    cudaGetSymbolAddress((void**)&norms, g_norms);
    cudaGetSymbolAddress((void**)&pbuf,  g_proj);

    float* z     = (float*)d_out;
    float* probs = (float*)d_out + (size_t)n * HH;

    // degree norms
    zero_kernel<<<cdiv(n, 256), 256>>>((float4*)norms, n);  // 4n floats
    deg4_kernel<<<dim3(cdiv(nE, 256), 4), 256>>>(srcp, dstp, srcn, dstn, norms, n, nE);
    norm_kernel<<<cdiv(4 * n, 256), 256>>>(norms, 4 * n);

    const int gGemm = cdiv(n, 64);
    const int gZero = cdiv((long long)2 * n * 16, 256);
    const int gAggr = cdiv((long long)nE * 16, 256);

    // layer 1: y_rel = c_src_rel ⊙ (x @ W0_rel), both relations in one kernel
    gemm_x_dual<<<gGemm, 256>>>(x, norms, norms + 2 * (size_t)n, W0p, W0n,
                                y, y + (size_t)n * 64, n);
    zero_kernel<<<gZero, 256>>>((float4*)agg, 2 * n * 16);
    aggregate<<<dim3(gAggr, 2), 256>>>(y, srcp, dstp, srcn, dstn, agg, n, nE);

    // layer 2: fused relu-epilogue + GEMM, both relations
    gemm_l2<<<dim3(gGemm, 2), 256>>>(agg, norms, b0p, b0n, W1p, W1n, y, n);
    zero_kernel<<<gZero, 256>>>((float4*)agg, 2 * n * 16);
    aggregate<<<dim3(gAggr, 2), 256>>>(y, srcp, dstp, srcn, dstn, agg, n, nE);

    // z = relu(pos) - relu(neg) -> d_out
    combine<<<cdiv((long long)n * 16, 256), 256>>>(agg, norms, b1p, b1n, z, n);

    // classifier via per-node projections
    proj_kernel<<<cdiv(n, 8), 256>>>(z, Wc, pbuf, n);
    cls_kernel<<<cdiv(nQ, 256), 256>>>(pbuf, ei, bc, probs, nQ);
}

// round 3
// speedup vs baseline: 2.5329x; 1.6834x over previous
#include <cuda_runtime.h>
#include <math.h>

#define NN 100000
#define EE 1600000
#define HH 64

typedef unsigned long long u64;

// ---------------- scratch (device globals) ----------------------------------
__device__ float g_y[2 * (size_t)NN * HH];   // GEMM outputs [rel][N][64]
__device__ float g_h[2 * (size_t)NN * HH];   // layer-1 activations [rel][N][64]
__device__ float g_norms[4 * NN];            // csp | cdp | csn | cdn
__device__ int   g_cnt[4 * NN];              // int degree counts (same layout)
__device__ int   g_off[2 * (NN + 1)];        // CSR row offsets (dst) per relation
__device__ int   g_cur[2 * NN];              // scatter cursors
__device__ int   g_csr[2 * EE];              // src ids grouped by dst
__device__ int   g_bsum[2 * 128];            // scan block sums
__device__ float g_proj[4 * NN];             // classifier projections [N][4]

// ---------------- packed fp32x2 ---------------------------------------------
__device__ __forceinline__ u64 pack2(float a, float b) {
    u64 r; asm("mov.b64 %0, {%1,%2};" : "=l"(r) : "f"(a), "f"(b)); return r;
}
__device__ __forceinline__ void fma2(u64& d, u64 a, u64 b) {
    asm("fma.rn.f32x2 %0, %1, %2, %3;" : "=l"(d) : "l"(a), "l"(b), "l"(d));
}
__device__ __forceinline__ u64 mul2(u64 a, u64 b) {
    u64 r; asm("mul.rn.f32x2 %0, %1, %2;" : "=l"(r) : "l"(a), "l"(b)); return r;
}

// ---------------- utility ----------------------------------------------------
__global__ void zero_int4(int4* __restrict__ p, int n4) {
    int t = blockIdx.x * blockDim.x + threadIdx.x;
    if (t < n4) p[t] = make_int4(0, 0, 0, 0);
}

__global__ void deg4_kernel(const int* __restrict__ sp, const int* __restrict__ dp,
                            const int* __restrict__ sn, const int* __restrict__ dn,
                            int* __restrict__ cnt, int n, int nE) {
    int t = blockIdx.x * blockDim.x + threadIdx.x;
    if (t >= nE) return;
    int w = blockIdx.y;
    const int* idx = (w == 0) ? sp : (w == 1) ? dp : (w == 2) ? sn : dn;
    atomicAdd(cnt + (size_t)w * n + idx[t], 1);
}

__global__ void norm_kernel(const int* __restrict__ cnt, float* __restrict__ norms, int n4) {
    int t = blockIdx.x * blockDim.x + threadIdx.x;
    if (t < n4) {
        int d = cnt[t];
        norms[t] = (d > 0) ? rsqrtf((float)d) : 0.f;
    }
}

// ---------------- prefix scan of dst counts (3 kernels) ----------------------
// counts for relation rel live at cnt + (1+2*rel)*n. nb = ceil(n/1024) blocks.
__global__ void scan_partial(const int* __restrict__ cnt, int* __restrict__ bsum, int n) {
    int rel = blockIdx.y;
    const int* c = cnt + (size_t)(1 + 2 * rel) * n;
    int tid = threadIdx.x;
    int base = blockIdx.x * 1024 + tid * 4;
    int s = 0;
    #pragma unroll
    for (int j = 0; j < 4; j++) { int i = base + j; if (i < n) s += c[i]; }
    __shared__ int sm[256];
    sm[tid] = s; __syncthreads();
    for (int o = 128; o > 0; o >>= 1) {
        if (tid < o) sm[tid] += sm[tid + o];
        __syncthreads();
    }
    if (tid == 0) bsum[rel * 128 + blockIdx.x] = sm[0];
}

__global__ void scan_blocksums(int* __restrict__ bsum, int* __restrict__ off,
                               int n, int nb, int nEp, int nEn) {
    int rel = blockIdx.x;
    int tid = threadIdx.x;   // 128 threads
    __shared__ int sm[128];
    int v = (tid < nb) ? bsum[rel * 128 + tid] : 0;
    sm[tid] = v; __syncthreads();
    for (int o = 1; o < 128; o <<= 1) {
        int a = (tid >= o) ? sm[tid - o] : 0;
        __syncthreads();
        sm[tid] += a;
        __syncthreads();
    }
    bsum[rel * 128 + tid] = sm[tid] - v;   // exclusive
    if (tid == 0) off[(size_t)rel * (n + 1) + n] = rel ? nEn : nEp;
}

__global__ void scan_final(const int* __restrict__ cnt, const int* __restrict__ bsum,
                           int* __restrict__ off, int* __restrict__ cur, int n) {
    int rel = blockIdx.y;
    const int* c = cnt + (size_t)(1 + 2 * rel) * n;
    int* o = off + (size_t)rel * (n + 1);
    int* cu = cur + (size_t)rel * n;
    int tid = threadIdx.x;
    int base = blockIdx.x * 1024 + tid * 4;
    int v[4];
    #pragma unroll
    for (int j = 0; j < 4; j++) { int i = base + j; v[j] = (i < n) ? c[i] : 0; }
    int tsum = v[0] + v[1] + v[2] + v[3];
    __shared__ int sm[256];
    sm[tid] = tsum; __syncthreads();
    for (int ofs = 1; ofs < 256; ofs <<= 1) {
        int a = (tid >= ofs) ? sm[tid - ofs] : 0;
        __syncthreads();
        sm[tid] += a;
        __syncthreads();
    }
    int ex = bsum[rel * 128 + blockIdx.x] + sm[tid] - tsum;
    #pragma unroll
    for (int j = 0; j < 4; j++) {
        int i = base + j;
        if (i < n) { o[i] = ex; cu[i] = ex; }
        ex += v[j];
    }
}

__global__ void scatter_kernel(const int* __restrict__ src, const int* __restrict__ dst,
                               int* __restrict__ cur, int* __restrict__ csr, int nE) {
    int e = blockIdx.x * blockDim.x + threadIdx.x;
    if (e >= nE) return;
    int d = dst[e];
    int p = atomicAdd(cur + d, 1);
    csr[p] = src[e];
}

// ---------------- GEMM: Y_rel[i,:] = c_rel[i] * (X_rel[i,:] @ W_rel) ---------
// grid (ceil(n/64), 2). block 256. warp: 32 rows x 16 cols, W broadcast-LDS.
__global__ void __launch_bounds__(256)
gemm_rel(const float* __restrict__ X0, const float* __restrict__ X1,
         const float* __restrict__ norms, const float* __restrict__ W0,
         const float* __restrict__ W1, float* __restrict__ Y, int n) {
    int rel = blockIdx.y;
    const float* X = rel ? X1 : X0;
    const float* cs = norms + 2 * (size_t)rel * n;
    const float* W  = rel ? W1 : W0;
    float* Yo = Y + (size_t)rel * n * 64;

    __shared__ float Ws[4096];      // W row-major [k][col]
    __shared__ float Xs[4096];      // transposed: Xs[k*64 + r]
    int tid = threadIdx.x;
    int row0 = blockIdx.x * 64;

    #pragma unroll
    for (int i = tid; i < 1024; i += 256) ((float4*)Ws)[i] = ((const float4*)W)[i];
    for (int i = tid; i < 1024; i += 256) {
        int r = i & 63, kq = i >> 6;               // kq: which float4 of the row
        int gr = row0 + r;
        float4 v = (gr < n) ? ((const float4*)X)[(size_t)gr * 16 + kq]
                            : make_float4(0.f, 0.f, 0.f, 0.f);
        Xs[(4 * kq + 0) * 64 + r] = v.x;
        Xs[(4 * kq + 1) * 64 + r] = v.y;
        Xs[(4 * kq + 2) * 64 + r] = v.z;
        Xs[(4 * kq + 3) * 64 + r] = v.w;
    }
    __syncthreads();

    int w = tid >> 5, lane = tid & 31;
    int r = (w >> 2) * 32 + lane;        // row within block (0..63)
    int cg = (w & 3) * 16;               // column group base
    u64 acc[8] = {0, 0, 0, 0, 0, 0, 0, 0};

    #pragma unroll
    for (int k = 0; k < 64; k++) {
        float xv = Xs[k * 64 + r];                 // conflict-free LDS.32
        u64 X2 = pack2(xv, xv);
        const float* wr = &Ws[k * 64 + cg];        // uniform across warp -> broadcast
        ulonglong2 wa = *(const ulonglong2*)(wr + 0);
        ulonglong2 wb = *(const ulonglong2*)(wr + 4);
        ulonglong2 wc = *(const ulonglong2*)(wr + 8);
        ulonglong2 wd = *(const ulonglong2*)(wr + 12);
        fma2(acc[0], X2, wa.x); fma2(acc[1], X2, wa.y);
        fma2(acc[2], X2, wb.x); fma2(acc[3], X2, wb.y);
        fma2(acc[4], X2, wc.x); fma2(acc[5], X2, wc.y);
        fma2(acc[6], X2, wd.x); fma2(acc[7], X2, wd.y);
    }

    int gr = row0 + r;
    if (gr < n) {
        u64 c2 = pack2(cs[gr], cs[gr]);
        ulonglong2 o;
        float* yo = Yo + (size_t)gr * 64 + cg;
        o.x = mul2(acc[0], c2); o.y = mul2(acc[1], c2); *(ulonglong2*)(yo + 0) = o;
        o.x = mul2(acc[2], c2); o.y = mul2(acc[3], c2); *(ulonglong2*)(yo + 4) = o;
        o.x = mul2(acc[4], c2); o.y = mul2(acc[5], c2); *(ulonglong2*)(yo + 8) = o;
        o.x = mul2(acc[6], c2); o.y = mul2(acc[7], c2); *(ulonglong2*)(yo + 12) = o;
    }
}

// ---------------- CSR pull aggregation ---------------------------------------
__device__ __forceinline__ float2 csr_sum(const int* __restrict__ off,
                                          const int* __restrict__ csr,
                                          const float* __restrict__ ylane, int node) {
    int j = off[node], end = off[node + 1];
    float2 a0 = make_float2(0.f, 0.f), a1 = make_float2(0.f, 0.f);
    for (; j + 2 <= end; j += 2) {
        int s0 = __ldg(csr + j);
        int s1 = __ldg(csr + j + 1);
        float2 v0 = *(const float2*)(ylane + (size_t)s0 * 64);
        float2 v1 = *(const float2*)(ylane + (size_t)s1 * 64);
        a0.x += v0.x; a0.y += v0.y;
        a1.x += v1.x; a1.y += v1.y;
    }
    if (j < end) {
        int s = __ldg(csr + j);
        float2 v = *(const float2*)(ylane + (size_t)s * 64);
        a0.x += v.x; a0.y += v.y;
    }
    a0.x += a1.x; a0.y += a1.y;
    return a0;
}

// layer 1: h_rel[i,:] = relu(c_dst[i] * sum_{e: dst=i} y_rel[src] + b0_rel)
__global__ void agg_l1(const float* __restrict__ y, const int* __restrict__ off,
                       const int* __restrict__ csr, const float* __restrict__ norms,
                       const float* __restrict__ b0p, const float* __restrict__ b0n,
                       float* __restrict__ h, int n) {
    int rel = blockIdx.y;
    int node = blockIdx.x * 8 + (threadIdx.x >> 5);
    if (node >= n) return;
    int lane = threadIdx.x & 31;
    const float* yl = y + (size_t)rel * n * 64 + lane * 2;
    float2 a = csr_sum(off + (size_t)rel * (n + 1), csr + (size_t)rel * EE, yl, node);
    float c = norms[(size_t)(1 + 2 * rel) * n + node];
    const float* b = rel ? b0n : b0p;
    float2 r;
    r.x = fmaxf(c * a.x + b[2 * lane + 0], 0.f);
    r.y = fmaxf(c * a.y + b[2 * lane + 1], 0.f);
    *(float2*)(h + (size_t)rel * n * 64 + (size_t)node * 64 + lane * 2) = r;
}

// layer 2 fused: z = relu(cdp*sumP + b1p) - relu(cdn*sumN + b1n)
__global__ void agg_l2(const float* __restrict__ y, const int* __restrict__ off,
                       const int* __restrict__ csr, const float* __restrict__ norms,
                       const float* __restrict__ b1p, const float* __restrict__ b1n,
                       float* __restrict__ z, int n) {
    int node = blockIdx.x * 8 + (threadIdx.x >> 5);
    if (node >= n) return;
    int lane = threadIdx.x & 31;
    float2 aP = csr_sum(off, csr, y + lane * 2, node);
    float2 aN = csr_sum(off + (n + 1), csr + (size_t)EE, y + (size_t)n * 64 + lane * 2, node);
    float cp = norms[(size_t)n + node];
    float cn = norms[3 * (size_t)n + node];
    float2 r;
    r.x = fmaxf(cp * aP.x + b1p[2 * lane + 0], 0.f) - fmaxf(cn * aN.x + b1n[2 * lane + 0], 0.f);
    r.y = fmaxf(cp * aP.y + b1p[2 * lane + 1], 0.f) - fmaxf(cn * aN.y + b1n[2 * lane + 1], 0.f);
    *(float2*)(z + (size_t)node * 64 + lane * 2) = r;
}

// ---------------- classifier --------------------------------------------------
__global__ void proj_kernel(const float* __restrict__ z, const float* __restrict__ Wc,
                            float* __restrict__ p, int n) {
    __shared__ float Wcs[256];
    int tid = threadIdx.x;
    Wcs[tid] = Wc[tid];
    __syncthreads();
    int warp = (blockIdx.x * 256 + tid) >> 5;
    int lane = tid & 31;
    if (warp >= n) return;
    float z0 = z[(size_t)warp * 64 + lane];
    float z1 = z[(size_t)warp * 64 + 32 + lane];
    float s0 = z0 * Wcs[lane * 2 + 0] + z1 * Wcs[(lane + 32) * 2 + 0];
    float s1 = z0 * Wcs[lane * 2 + 1] + z1 * Wcs[(lane + 32) * 2 + 1];
    float d0 = z0 * Wcs[128 + lane * 2 + 0] + z1 * Wcs[128 + (lane + 32) * 2 + 0];
    float d1 = z0 * Wcs[128 + lane * 2 + 1] + z1 * Wcs[128 + (lane + 32) * 2 + 1];
    #pragma unroll
    for (int o = 16; o > 0; o >>= 1) {
        s0 += __shfl_xor_sync(0xffffffffu, s0, o);
        s1 += __shfl_xor_sync(0xffffffffu, s1, o);
        d0 += __shfl_xor_sync(0xffffffffu, d0, o);
        d1 += __shfl_xor_sync(0xffffffffu, d1, o);
    }
    if (lane == 0) ((float4*)p)[warp] = make_float4(s0, s1, d0, d1);
}

__global__ void cls_kernel(const float* __restrict__ p, const int* __restrict__ ei,
                           const float* __restrict__ bc, float* __restrict__ out, int nQ) {
    int q = blockIdx.x * blockDim.x + threadIdx.x;
    if (q >= nQ) return;
    int s = __ldg(ei + q);
    int d = __ldg(ei + nQ + q);
    float4 ps = ((const float4*)p)[s];
    float4 pd = ((const float4*)p)[d];
    float l0 = ps.x + pd.z + bc[0];
    float l1 = ps.y + pd.w + bc[1];
    float2 o;
    o.x = 1.f / (1.f + expf(-l0));
    o.y = 1.f / (1.f + expf(-l1));
    ((float2*)out)[q] = o;
}

// ---------------- launch -------------------------------------------------------
static inline int cdiv(long long a, int b) { return (int)((a + b - 1) / b); }

extern "C" void kernel_launch(void* const* d_in, const int* in_sizes, int n_in,
                              void* d_out, int out_size) {
    const float* x    = (const float*)d_in[0];
    const float* W0p  = (const float*)d_in[1];
    const float* b0p  = (const float*)d_in[2];
    const float* W0n  = (const float*)d_in[3];
    const float* b0n  = (const float*)d_in[4];
    const float* W1p  = (const float*)d_in[5];
    const float* b1p  = (const float*)d_in[6];
    const float* W1n  = (const float*)d_in[7];
    const float* b1n  = (const float*)d_in[8];
    const float* Wc   = (const float*)d_in[9];
    const float* bc   = (const float*)d_in[10];
    const int*   srcp = (const int*)d_in[11];
    const int*   dstp = (const int*)d_in[12];
    const int*   srcn = (const int*)d_in[13];
    const int*   dstn = (const int*)d_in[14];
    const int*   ei   = (const int*)d_in[15];

    const int n   = in_sizes[0] / HH;    // 100000
    const int nEp = in_sizes[11];
    const int nEn = in_sizes[13];
    const int nQ  = in_sizes[15] / 2;

    float *y, *h, *norms, *pbuf;
    int *cnt, *off, *cur, *csr, *bsum;
    cudaGetSymbolAddress((void**)&y,     g_y);
    cudaGetSymbolAddress((void**)&h,     g_h);
    cudaGetSymbolAddress((void**)&norms, g_norms);
    cudaGetSymbolAddress((void**)&cnt,   g_cnt);
    cudaGetSymbolAddress((void**)&off,   g_off);
    cudaGetSymbolAddress((void**)&cur,   g_cur);
    cudaGetSymbolAddress((void**)&csr,   g_csr);
    cudaGetSymbolAddress((void**)&bsum,  g_bsum);
    cudaGetSymbolAddress((void**)&pbuf,  g_proj);

    float* z     = (float*)d_out;
    float* probs = (float*)d_out + (size_t)n * HH;

    const int nb = cdiv(n, 1024);       // 98 (<=128 required)

    // degrees + norms + CSR
    zero_int4<<<cdiv(n, 256), 256>>>((int4*)cnt, n);                 // 4n ints
    deg4_kernel<<<dim3(cdiv(nEp, 256), 4), 256>>>(srcp, dstp, srcn, dstn, cnt, n, nEp);
    norm_kernel<<<cdiv(4 * n, 256), 256>>>(cnt, norms, 4 * n);
    scan_partial<<<dim3(nb, 2), 256>>>(cnt, bsum, n);
    scan_blocksums<<<2, 128>>>(bsum, off, n, nb, nEp, nEn);
    scan_final<<<dim3(nb, 2), 256>>>(cnt, bsum, off, cur, n);
    scatter_kernel<<<cdiv(nEp, 256), 256>>>(srcp, dstp, cur, csr, nEp);
    scatter_kernel<<<cdiv(nEn, 256), 256>>>(srcn, dstn, cur + n, csr + (size_t)EE, nEn);

    const int gGemm = cdiv(n, 64);
    const int gAgg  = cdiv(n, 8);

    // layer 1
    gemm_rel<<<dim3(gGemm, 2), 256>>>(x, x, norms, W0p, W0n, y, n);
    agg_l1<<<dim3(gAgg, 2), 256>>>(y, off, csr, norms, b0p, b0n, h, n);

    // layer 2 (reads h per relation), fused combine into d_out
    gemm_rel<<<dim3(gGemm, 2), 256>>>(h, h + (size_t)n * 64, norms, W1p, W1n, y, n);
    agg_l2<<<gAgg, 256>>>(y, off, csr, norms, b1p, b1n, z, n);

    // classifier
    proj_kernel<<<cdiv(n, 8), 256>>>(z, Wc, pbuf, n);
    cls_kernel<<<cdiv(nQ, 256), 256>>>(pbuf, ei, bc, probs, nQ);
}

// round 4
// speedup vs baseline: 2.8438x; 1.1227x over previous
#include <cuda_runtime.h>
#include <cuda_fp16.h>
#include <math.h>

#define NN 100000
#define EE 1600000
#define HH 64

typedef unsigned long long u64;

// ---------------- scratch (device globals) ----------------------------------
__device__ __half g_y[2 * (size_t)NN * HH];  // GEMM outputs [rel][N][64] (fp16)
__device__ float  g_h[2 * (size_t)NN * HH];  // layer-1 activations [rel][N][64]
__device__ float  g_norms[4 * NN];           // csp | cdp | csn | cdn
__device__ int    g_cnt[4 * NN];             // int degree counts (same layout)
__device__ int    g_off[2 * (NN + 1)];       // CSR row offsets (dst) per relation
__device__ int    g_cur[2 * NN];             // scatter cursors
__device__ int    g_csr[2 * EE];             // src ids grouped by dst
__device__ int    g_bsum[2 * 128];           // scan block sums
__device__ float  g_proj[4 * NN];            // classifier projections [N][4]

// ---------------- packed fp32x2 ---------------------------------------------
__device__ __forceinline__ u64 pack2(float a, float b) {
    u64 r; asm("mov.b64 %0, {%1,%2};" : "=l"(r) : "f"(a), "f"(b)); return r;
}
__device__ __forceinline__ float2 unpk2(u64 v) {
    float2 f; asm("mov.b64 {%0,%1}, %2;" : "=f"(f.x), "=f"(f.y) : "l"(v)); return f;
}
__device__ __forceinline__ void fma2(u64& d, u64 a, u64 b) {
    asm("fma.rn.f32x2 %0, %1, %2, %3;" : "=l"(d) : "l"(a), "l"(b), "l"(d));
}

// ---------------- utility ----------------------------------------------------
__global__ void zero_int4(int4* __restrict__ p, int n4) {
    int t = blockIdx.x * blockDim.x + threadIdx.x;
    if (t < n4) p[t] = make_int4(0, 0, 0, 0);
}

__global__ void deg4_kernel(const int* __restrict__ sp, const int* __restrict__ dp,
                            const int* __restrict__ sn, const int* __restrict__ dn,
                            int* __restrict__ cnt, int n, int nE) {
    int t = blockIdx.x * blockDim.x + threadIdx.x;
    if (t >= nE) return;
    int w = blockIdx.y;
    const int* idx = (w == 0) ? sp : (w == 1) ? dp : (w == 2) ? sn : dn;
    atomicAdd(cnt + (size_t)w * n + idx[t], 1);
}

__global__ void norm_kernel(const int* __restrict__ cnt, float* __restrict__ norms, int n4) {
    int t = blockIdx.x * blockDim.x + threadIdx.x;
    if (t < n4) {
        int d = cnt[t];
        norms[t] = (d > 0) ? rsqrtf((float)d) : 0.f;
    }
}

// ---------------- prefix scan of dst counts ----------------------------------
__global__ void scan_partial(const int* __restrict__ cnt, int* __restrict__ bsum, int n) {
    int rel = blockIdx.y;
    const int* c = cnt + (size_t)(1 + 2 * rel) * n;
    int tid = threadIdx.x;
    int base = blockIdx.x * 1024 + tid * 4;
    int s = 0;
    #pragma unroll
    for (int j = 0; j < 4; j++) { int i = base + j; if (i < n) s += c[i]; }
    __shared__ int sm[256];
    sm[tid] = s; __syncthreads();
    for (int o = 128; o > 0; o >>= 1) {
        if (tid < o) sm[tid] += sm[tid + o];
        __syncthreads();
    }
    if (tid == 0) bsum[rel * 128 + blockIdx.x] = sm[0];
}

__global__ void scan_blocksums(int* __restrict__ bsum, int* __restrict__ off,
                               int n, int nb, int nEp, int nEn) {
    int rel = blockIdx.x;
    int tid = threadIdx.x;   // 128 threads
    __shared__ int sm[128];
    int v = (tid < nb) ? bsum[rel * 128 + tid] : 0;
    sm[tid] = v; __syncthreads();
    for (int o = 1; o < 128; o <<= 1) {
        int a = (tid >= o) ? sm[tid - o] : 0;
        __syncthreads();
        sm[tid] += a;
        __syncthreads();
    }
    bsum[rel * 128 + tid] = sm[tid] - v;   // exclusive
    if (tid == 0) off[(size_t)rel * (n + 1) + n] = rel ? nEn : nEp;
}

__global__ void scan_final(const int* __restrict__ cnt, const int* __restrict__ bsum,
                           int* __restrict__ off, int* __restrict__ cur, int n) {
    int rel = blockIdx.y;
    const int* c = cnt + (size_t)(1 + 2 * rel) * n;
    int* o = off + (size_t)rel * (n + 1);
    int* cu = cur + (size_t)rel * n;
    int tid = threadIdx.x;
    int base = blockIdx.x * 1024 + tid * 4;
    int v[4];
    #pragma unroll
    for (int j = 0; j < 4; j++) { int i = base + j; v[j] = (i < n) ? c[i] : 0; }
    int tsum = v[0] + v[1] + v[2] + v[3];
    __shared__ int sm[256];
    sm[tid] = tsum; __syncthreads();
    for (int ofs = 1; ofs < 256; ofs <<= 1) {
        int a = (tid >= ofs) ? sm[tid - ofs] : 0;
        __syncthreads();
        sm[tid] += a;
        __syncthreads();
    }
    int ex = bsum[rel * 128 + blockIdx.x] + sm[tid] - tsum;
    #pragma unroll
    for (int j = 0; j < 4; j++) {
        int i = base + j;
        if (i < n) { o[i] = ex; cu[i] = ex; }
        ex += v[j];
    }
}

// both relations in one launch (grid.y)
__global__ void scatter2_kernel(const int* __restrict__ srcp, const int* __restrict__ dstp,
                                const int* __restrict__ srcn, const int* __restrict__ dstn,
                                int* __restrict__ cur, int* __restrict__ csr,
                                int n, int nEp, int nEn) {
    int rel = blockIdx.y;
    const int* src = rel ? srcn : srcp;
    const int* dst = rel ? dstn : dstp;
    int nE = rel ? nEn : nEp;
    int e = blockIdx.x * blockDim.x + threadIdx.x;
    if (e >= nE) return;
    int d = dst[e];
    int p = atomicAdd(cur + (size_t)rel * n + d, 1);
    csr[(size_t)rel * EE + p] = src[e];
}

// ---------------- GEMM: Y_rel[i,:] = half(c_rel[i] * (X_rel[i,:] @ W_rel)) ---
// grid (ceil(n/64), 2). block 256. warp: 32 rows x 16 cols, W broadcast-LDS.
__global__ void __launch_bounds__(256)
gemm_rel(const float* __restrict__ X0, const float* __restrict__ X1,
         const float* __restrict__ norms, const float* __restrict__ W0,
         const float* __restrict__ W1, __half* __restrict__ Y, int n) {
    int rel = blockIdx.y;
    const float* X = rel ? X1 : X0;
    const float* cs = norms + 2 * (size_t)rel * n;
    const float* W  = rel ? W1 : W0;
    __half* Yo = Y + (size_t)rel * n * 64;

    __shared__ float Ws[4096];      // W row-major [k][col]
    __shared__ float Xs[4096];      // transposed: Xs[k*64 + r]
    int tid = threadIdx.x;
    int row0 = blockIdx.x * 64;

    #pragma unroll
    for (int i = tid; i < 1024; i += 256) ((float4*)Ws)[i] = ((const float4*)W)[i];
    for (int i = tid; i < 1024; i += 256) {
        int r = i & 63, kq = i >> 6;
        int gr = row0 + r;
        float4 v = (gr < n) ? ((const float4*)X)[(size_t)gr * 16 + kq]
                            : make_float4(0.f, 0.f, 0.f, 0.f);
        Xs[(4 * kq + 0) * 64 + r] = v.x;
        Xs[(4 * kq + 1) * 64 + r] = v.y;
        Xs[(4 * kq + 2) * 64 + r] = v.z;
        Xs[(4 * kq + 3) * 64 + r] = v.w;
    }
    __syncthreads();

    int w = tid >> 5, lane = tid & 31;
    int r = (w >> 2) * 32 + lane;
    int cg = (w & 3) * 16;
    u64 acc[8] = {0, 0, 0, 0, 0, 0, 0, 0};

    #pragma unroll
    for (int k = 0; k < 64; k++) {
        float xv = Xs[k * 64 + r];
        u64 X2 = pack2(xv, xv);
        const float* wr = &Ws[k * 64 + cg];
        ulonglong2 wa = *(const ulonglong2*)(wr + 0);
        ulonglong2 wb = *(const ulonglong2*)(wr + 4);
        ulonglong2 wc = *(const ulonglong2*)(wr + 8);
        ulonglong2 wd = *(const ulonglong2*)(wr + 12);
        fma2(acc[0], X2, wa.x); fma2(acc[1], X2, wa.y);
        fma2(acc[2], X2, wb.x); fma2(acc[3], X2, wb.y);
        fma2(acc[4], X2, wc.x); fma2(acc[5], X2, wc.y);
        fma2(acc[6], X2, wd.x); fma2(acc[7], X2, wd.y);
    }

    int gr = row0 + r;
    if (gr < n) {
        float c = cs[gr];
        __half2 o[8];
        #pragma unroll
        for (int i = 0; i < 8; i++) {
            float2 f = unpk2(acc[i]);
            o[i] = __floats2half2_rn(f.x * c, f.y * c);
        }
        __half* yo = Yo + (size_t)gr * 64 + cg;
        *(uint4*)(yo + 0) = *(const uint4*)&o[0];   // 8 halves
        *(uint4*)(yo + 8) = *(const uint4*)&o[4];   // 8 halves
    }
}

// ---------------- CSR pull aggregation (fp16 payload, fp32 accum) ------------
__device__ __forceinline__ float2 csr_sum(const int* __restrict__ off,
                                          const int* __restrict__ csr,
                                          const __half2* __restrict__ ylane, int node) {
    int j = off[node], end = off[node + 1];
    float2 a0 = make_float2(0.f, 0.f), a1 = make_float2(0.f, 0.f);
    for (; j + 2 <= end; j += 2) {
        int s0 = __ldg(csr + j);
        int s1 = __ldg(csr + j + 1);
        float2 v0 = __half22float2(__ldg(ylane + (size_t)s0 * 32));
        float2 v1 = __half22float2(__ldg(ylane + (size_t)s1 * 32));
        a0.x += v0.x; a0.y += v0.y;
        a1.x += v1.x; a1.y += v1.y;
    }
    if (j < end) {
        int s = __ldg(csr + j);
        float2 v = __half22float2(__ldg(ylane + (size_t)s * 32));
        a0.x += v.x; a0.y += v.y;
    }
    a0.x += a1.x; a0.y += a1.y;
    return a0;
}

// layer 1: h_rel[i,:] = relu(c_dst[i] * sum y_rel[src] + b0_rel)
__global__ void agg_l1(const __half* __restrict__ y, const int* __restrict__ off,
                       const int* __restrict__ csr, const float* __restrict__ norms,
                       const float* __restrict__ b0p, const float* __restrict__ b0n,
                       float* __restrict__ h, int n) {
    int rel = blockIdx.y;
    int node = blockIdx.x * 8 + (threadIdx.x >> 5);
    if (node >= n) return;
    int lane = threadIdx.x & 31;
    const __half2* yl = (const __half2*)(y + (size_t)rel * n * 64) + lane;
    float2 a = csr_sum(off + (size_t)rel * (n + 1), csr + (size_t)rel * EE, yl, node);
    float c = norms[(size_t)(1 + 2 * rel) * n + node];
    const float* b = rel ? b0n : b0p;
    float2 r;
    r.x = fmaxf(c * a.x + b[2 * lane + 0], 0.f);
    r.y = fmaxf(c * a.y + b[2 * lane + 1], 0.f);
    *(float2*)(h + (size_t)rel * n * 64 + (size_t)node * 64 + lane * 2) = r;
}

// layer 2 fused: z = relu(cdp*sumP + b1p) - relu(cdn*sumN + b1n)
// + fused classifier projection p[node] = [z@Wc_src, z@Wc_dst]
__global__ void agg_l2(const __half* __restrict__ y, const int* __restrict__ off,
                       const int* __restrict__ csr, const float* __restrict__ norms,
                       const float* __restrict__ b1p, const float* __restrict__ b1n,
                       const float* __restrict__ Wc,
                       float* __restrict__ z, float* __restrict__ proj, int n) {
    int node = blockIdx.x * 8 + (threadIdx.x >> 5);
    if (node >= n) return;
    int lane = threadIdx.x & 31;
    const __half2* ylP = (const __half2*)y + lane;
    const __half2* ylN = (const __half2*)(y + (size_t)n * 64) + lane;
    float2 aP = csr_sum(off, csr, ylP, node);
    float2 aN = csr_sum(off + (n + 1), csr + (size_t)EE, ylN, node);
    float cp = norms[(size_t)n + node];
    float cn = norms[3 * (size_t)n + node];
    float2 r;
    r.x = fmaxf(cp * aP.x + b1p[2 * lane + 0], 0.f) - fmaxf(cn * aN.x + b1n[2 * lane + 0], 0.f);
    r.y = fmaxf(cp * aP.y + b1p[2 * lane + 1], 0.f) - fmaxf(cn * aN.y + b1n[2 * lane + 1], 0.f);
    *(float2*)(z + (size_t)node * 64 + lane * 2) = r;

    // classifier projections (Wc is [128][2] row-major)
    int k = 2 * lane;
    float s0 = r.x * __ldg(Wc + k * 2 + 0) + r.y * __ldg(Wc + (k + 1) * 2 + 0);
    float s1 = r.x * __ldg(Wc + k * 2 + 1) + r.y * __ldg(Wc + (k + 1) * 2 + 1);
    float d0 = r.x * __ldg(Wc + (128 + k * 2) + 0) + r.y * __ldg(Wc + (128 + (k + 1) * 2) + 0);
    float d1 = r.x * __ldg(Wc + (128 + k * 2) + 1) + r.y * __ldg(Wc + (128 + (k + 1) * 2) + 1);
    #pragma unroll
    for (int o = 16; o > 0; o >>= 1) {
        s0 += __shfl_xor_sync(0xffffffffu, s0, o);
        s1 += __shfl_xor_sync(0xffffffffu, s1, o);
        d0 += __shfl_xor_sync(0xffffffffu, d0, o);
        d1 += __shfl_xor_sync(0xffffffffu, d1, o);
    }
    if (lane == 0) ((float4*)proj)[node] = make_float4(s0, s1, d0, d1);
}

// ---------------- classifier: 2 x 16B per query ------------------------------
__global__ void cls_kernel(const float* __restrict__ p, const int* __restrict__ ei,
                           const float* __restrict__ bc, float* __restrict__ out, int nQ) {
    int q = blockIdx.x * blockDim.x + threadIdx.x;
    if (q >= nQ) return;
    int s = __ldg(ei + q);
    int d = __ldg(ei + nQ + q);
    float4 ps = ((const float4*)p)[s];
    float4 pd = ((const float4*)p)[d];
    float l0 = ps.x + pd.z + bc[0];
    float l1 = ps.y + pd.w + bc[1];
    float2 o;
    o.x = 1.f / (1.f + expf(-l0));
    o.y = 1.f / (1.f + expf(-l1));
    ((float2*)out)[q] = o;
}

// ---------------- launch -------------------------------------------------------
static inline int cdiv(long long a, int b) { return (int)((a + b - 1) / b); }

extern "C" void kernel_launch(void* const* d_in, const int* in_sizes, int n_in,
                              void* d_out, int out_size) {
    const float* x    = (const float*)d_in[0];
    const float* W0p  = (const float*)d_in[1];
    const float* b0p  = (const float*)d_in[2];
    const float* W0n  = (const float*)d_in[3];
    const float* b0n  = (const float*)d_in[4];
    const float* W1p  = (const float*)d_in[5];
    const float* b1p  = (const float*)d_in[6];
    const float* W1n  = (const float*)d_in[7];
    const float* b1n  = (const float*)d_in[8];
    const float* Wc   = (const float*)d_in[9];
    const float* bc   = (const float*)d_in[10];
    const int*   srcp = (const int*)d_in[11];
    const int*   dstp = (const int*)d_in[12];
    const int*   srcn = (const int*)d_in[13];
    const int*   dstn = (const int*)d_in[14];
    const int*   ei   = (const int*)d_in[15];

    const int n   = in_sizes[0] / HH;
    const int nEp = in_sizes[11];
    const int nEn = in_sizes[13];
    const int nQ  = in_sizes[15] / 2;

    __half* y;
    float *h, *norms, *pbuf;
    int *cnt, *off, *cur, *csr, *bsum;
    cudaGetSymbolAddress((void**)&y,     g_y);
    cudaGetSymbolAddress((void**)&h,     g_h);
    cudaGetSymbolAddress((void**)&norms, g_norms);
    cudaGetSymbolAddress((void**)&cnt,   g_cnt);
    cudaGetSymbolAddress((void**)&off,   g_off);
    cudaGetSymbolAddress((void**)&cur,   g_cur);
    cudaGetSymbolAddress((void**)&csr,   g_csr);
    cudaGetSymbolAddress((void**)&bsum,  g_bsum);
    cudaGetSymbolAddress((void**)&pbuf,  g_proj);

    float* z     = (float*)d_out;
    float* probs = (float*)d_out + (size_t)n * HH;

    const int nb = cdiv(n, 1024);
    const int gE = cdiv(nEp > nEn ? nEp : nEn, 256);

    // degrees + norms + CSR
    zero_int4<<<cdiv(n, 256), 256>>>((int4*)cnt, n);
    deg4_kernel<<<dim3(cdiv(nEp, 256), 4), 256>>>(srcp, dstp, srcn, dstn, cnt, n, nEp);
    norm_kernel<<<cdiv(4 * n, 256), 256>>>(cnt, norms, 4 * n);
    scan_partial<<<dim3(nb, 2), 256>>>(cnt, bsum, n);
    scan_blocksums<<<2, 128>>>(bsum, off, n, nb, nEp, nEn);
    scan_final<<<dim3(nb, 2), 256>>>(cnt, bsum, off, cur, n);
    scatter2_kernel<<<dim3(gE, 2), 256>>>(srcp, dstp, srcn, dstn, cur, csr, n, nEp, nEn);

    const int gGemm = cdiv(n, 64);
    const int gAgg  = cdiv(n, 8);

    // layer 1
    gemm_rel<<<dim3(gGemm, 2), 256>>>(x, x, norms, W0p, W0n, y, n);
    agg_l1<<<dim3(gAgg, 2), 256>>>(y, off, csr, norms, b0p, b0n, h, n);

    // layer 2, fused combine + classifier projection
    gemm_rel<<<dim3(gGemm, 2), 256>>>(h, h + (size_t)n * 64, norms, W1p, W1n, y, n);
    agg_l2<<<gAgg, 256>>>(y, off, csr, norms, b1p, b1n, Wc, z, pbuf, n);

    // classifier
    cls_kernel<<<cdiv(nQ, 256), 256>>>(pbuf, ei, bc, probs, nQ);
}

// round 5
// speedup vs baseline: 2.8917x; 1.0169x over previous
#include <cuda_runtime.h>
#include <cuda_fp16.h>
#include <math.h>

#define NN 100000
#define EE 1600000
#define HH 64

typedef unsigned long long u64;

// ---------------- scratch (device globals) ----------------------------------
__device__ __half g_y[2 * (size_t)NN * HH];  // GEMM outputs [rel][N][64] (fp16)
__device__ __half g_h[2 * (size_t)NN * HH];  // layer-1 activations (fp16)
__device__ float  g_norms[4 * NN];           // csp | cdp | csn | cdn
__device__ int    g_cnt[4 * NN];             // int degree counts (same layout)
__device__ int    g_off[2 * (NN + 1)];       // CSR row offsets (dst) per relation
__device__ int    g_cur[2 * NN];             // scatter cursors
__device__ int    g_csr[2 * EE];             // src ids grouped by dst
__device__ int    g_bsum[2 * 128];           // scan block sums
__device__ float  g_proj[4 * NN];            // classifier projections [N][4]

// ---------------- packed fp32x2 ---------------------------------------------
__device__ __forceinline__ u64 pack2(float a, float b) {
    u64 r; asm("mov.b64 %0, {%1,%2};" : "=l"(r) : "f"(a), "f"(b)); return r;
}
__device__ __forceinline__ float2 unpk2(u64 v) {
    float2 f; asm("mov.b64 {%0,%1}, %2;" : "=f"(f.x), "=f"(f.y) : "l"(v)); return f;
}
__device__ __forceinline__ void fma2(u64& d, u64 a, u64 b) {
    asm("fma.rn.f32x2 %0, %1, %2, %3;" : "=l"(d) : "l"(a), "l"(b), "l"(d));
}

// ---------------- utility ----------------------------------------------------
__global__ void zero_int4(int4* __restrict__ p, int n4) {
    int t = blockIdx.x * blockDim.x + threadIdx.x;
    if (t < n4) p[t] = make_int4(0, 0, 0, 0);
}

__global__ void deg4_kernel(const int* __restrict__ sp, const int* __restrict__ dp,
                            const int* __restrict__ sn, const int* __restrict__ dn,
                            int* __restrict__ cnt, int n, int nE) {
    int t = blockIdx.x * blockDim.x + threadIdx.x;
    if (t >= nE) return;
    int w = blockIdx.y;
    const int* idx = (w == 0) ? sp : (w == 1) ? dp : (w == 2) ? sn : dn;
    atomicAdd(cnt + (size_t)w * n + idx[t], 1);
}

__global__ void norm_kernel(const int* __restrict__ cnt, float* __restrict__ norms, int n4) {
    int t = blockIdx.x * blockDim.x + threadIdx.x;
    if (t < n4) {
        int d = cnt[t];
        norms[t] = (d > 0) ? rsqrtf((float)d) : 0.f;
    }
}

// ---------------- prefix scan of dst counts ----------------------------------
__global__ void scan_partial(const int* __restrict__ cnt, int* __restrict__ bsum, int n) {
    int rel = blockIdx.y;
    const int* c = cnt + (size_t)(1 + 2 * rel) * n;
    int tid = threadIdx.x;
    int base = blockIdx.x * 1024 + tid * 4;
    int s = 0;
    #pragma unroll
    for (int j = 0; j < 4; j++) { int i = base + j; if (i < n) s += c[i]; }
    __shared__ int sm[256];
    sm[tid] = s; __syncthreads();
    for (int o = 128; o > 0; o >>= 1) {
        if (tid < o) sm[tid] += sm[tid + o];
        __syncthreads();
    }
    if (tid == 0) bsum[rel * 128 + blockIdx.x] = sm[0];
}

__global__ void scan_blocksums(int* __restrict__ bsum, int* __restrict__ off,
                               int n, int nb, int nEp, int nEn) {
    int rel = blockIdx.x;
    int tid = threadIdx.x;   // 128 threads
    __shared__ int sm[128];
    int v = (tid < nb) ? bsum[rel * 128 + tid] : 0;
    sm[tid] = v; __syncthreads();
    for (int o = 1; o < 128; o <<= 1) {
        int a = (tid >= o) ? sm[tid - o] : 0;
        __syncthreads();
        sm[tid] += a;
        __syncthreads();
    }
    bsum[rel * 128 + tid] = sm[tid] - v;   // exclusive
    if (tid == 0) off[(size_t)rel * (n + 1) + n] = rel ? nEn : nEp;
}

__global__ void scan_final(const int* __restrict__ cnt, const int* __restrict__ bsum,
                           int* __restrict__ off, int* __restrict__ cur, int n) {
    int rel = blockIdx.y;
    const int* c = cnt + (size_t)(1 + 2 * rel) * n;
    int* o = off + (size_t)rel * (n + 1);
    int* cu = cur + (size_t)rel * n;
    int tid = threadIdx.x;
    int base = blockIdx.x * 1024 + tid * 4;
    int v[4];
    #pragma unroll
    for (int j = 0; j < 4; j++) { int i = base + j; v[j] = (i < n) ? c[i] : 0; }
    int tsum = v[0] + v[1] + v[2] + v[3];
    __shared__ int sm[256];
    sm[tid] = tsum; __syncthreads();
    for (int ofs = 1; ofs < 256; ofs <<= 1) {
        int a = (tid >= ofs) ? sm[tid - ofs] : 0;
        __syncthreads();
        sm[tid] += a;
        __syncthreads();
    }
    int ex = bsum[rel * 128 + blockIdx.x] + sm[tid] - tsum;
    #pragma unroll
    for (int j = 0; j < 4; j++) {
        int i = base + j;
        if (i < n) { o[i] = ex; cu[i] = ex; }
        ex += v[j];
    }
}

// ---------------- shared GEMM body (fp32 or fp16 input) ----------------------
// block = 256 threads, 64 rows; warp: 32 rows x 16 cols, W broadcast-LDS.
template <typename T>
__device__ __forceinline__ void gemm_body(const T* __restrict__ X,
                                          const float* __restrict__ cs,
                                          const float* __restrict__ W,
                                          __half* __restrict__ Yo, int n, int blk) {
    __shared__ float Ws[4096];      // W row-major [k][col]
    __shared__ float Xs[4096];      // transposed: Xs[k*64 + r]
    int tid = threadIdx.x;
    int row0 = blk * 64;

    #pragma unroll
    for (int i = tid; i < 1024; i += 256) ((float4*)Ws)[i] = ((const float4*)W)[i];

    if (sizeof(T) == 4) {           // fp32 input
        const float* Xf = (const float*)X;
        for (int i = tid; i < 1024; i += 256) {
            int r = i & 63, kq = i >> 6;
            int gr = row0 + r;
            float4 v = (gr < n) ? ((const float4*)Xf)[(size_t)gr * 16 + kq]
                                : make_float4(0.f, 0.f, 0.f, 0.f);
            Xs[(4 * kq + 0) * 64 + r] = v.x;
            Xs[(4 * kq + 1) * 64 + r] = v.y;
            Xs[(4 * kq + 2) * 64 + r] = v.z;
            Xs[(4 * kq + 3) * 64 + r] = v.w;
        }
    } else {                        // fp16 input
        const __half* Xh = (const __half*)X;
        for (int i = tid; i < 512; i += 256) {
            int r = i & 63, ko = i >> 6;     // 8 uint4 (8 halves each) per row
            int gr = row0 + r;
            uint4 v = (gr < n) ? ((const uint4*)Xh)[(size_t)gr * 8 + ko]
                               : make_uint4(0, 0, 0, 0);
            const __half2* hp = (const __half2*)&v;
            #pragma unroll
            for (int q = 0; q < 4; q++) {
                float2 f = __half22float2(hp[q]);
                Xs[(8 * ko + 2 * q + 0) * 64 + r] = f.x;
                Xs[(8 * ko + 2 * q + 1) * 64 + r] = f.y;
            }
        }
    }
    __syncthreads();

    int w = tid >> 5, lane = tid & 31;
    int r = (w >> 2) * 32 + lane;
    int cg = (w & 3) * 16;
    u64 acc[8] = {0, 0, 0, 0, 0, 0, 0, 0};

    #pragma unroll
    for (int k = 0; k < 64; k++) {
        float xv = Xs[k * 64 + r];
        u64 X2 = pack2(xv, xv);
        const float* wr = &Ws[k * 64 + cg];
        ulonglong2 wa = *(const ulonglong2*)(wr + 0);
        ulonglong2 wb = *(const ulonglong2*)(wr + 4);
        ulonglong2 wc = *(const ulonglong2*)(wr + 8);
        ulonglong2 wd = *(const ulonglong2*)(wr + 12);
        fma2(acc[0], X2, wa.x); fma2(acc[1], X2, wa.y);
        fma2(acc[2], X2, wb.x); fma2(acc[3], X2, wb.y);
        fma2(acc[4], X2, wc.x); fma2(acc[5], X2, wc.y);
        fma2(acc[6], X2, wd.x); fma2(acc[7], X2, wd.y);
    }

    int gr = row0 + r;
    if (gr < n) {
        float c = cs[gr];
        __half2 o[8];
        #pragma unroll
        for (int i = 0; i < 8; i++) {
            float2 f = unpk2(acc[i]);
            o[i] = __floats2half2_rn(f.x * c, f.y * c);
        }
        __half* yo = Yo + (size_t)gr * 64 + cg;
        *(uint4*)(yo + 0) = *(const uint4*)&o[0];
        *(uint4*)(yo + 8) = *(const uint4*)&o[4];
    }
}

// ---------------- fat kernel: layer-1 GEMM (both rels) + CSR scatter ---------
__global__ void __launch_bounds__(256)
gemm1_scatter(const float* __restrict__ x, const float* __restrict__ norms,
              const float* __restrict__ W0, const float* __restrict__ W1,
              __half* __restrict__ Y,
              const int* __restrict__ srcp, const int* __restrict__ dstp,
              const int* __restrict__ srcn, const int* __restrict__ dstn,
              int* __restrict__ cur, int* __restrict__ csr,
              int n, int nEp, int nEn, int gGemm, int gScat) {
    int b = blockIdx.x;
    if (b < 2 * gGemm) {
        int rel = b / gGemm;
        gemm_body<float>(x, norms + 2 * (size_t)rel * n,
                         rel ? W1 : W0, Y + (size_t)rel * n * 64, n, b % gGemm);
    } else {
        int sb = b - 2 * gGemm;
        int rel = sb / gScat;
        int e = (sb % gScat) * 256 + threadIdx.x;
        int nE = rel ? nEn : nEp;
        if (e >= nE) return;
        const int* src = rel ? srcn : srcp;
        const int* dst = rel ? dstn : dstp;
        int d = dst[e];
        int p = atomicAdd(cur + (size_t)rel * n + d, 1);
        csr[(size_t)rel * EE + p] = src[e];
    }
}

// ---------------- layer-2 GEMM (fp16 input) ----------------------------------
__global__ void __launch_bounds__(256)
gemm_l2(const __half* __restrict__ h, const float* __restrict__ norms,
        const float* __restrict__ W0, const float* __restrict__ W1,
        __half* __restrict__ Y, int n) {
    int rel = blockIdx.y;
    gemm_body<__half>(h + (size_t)rel * n * 64, norms + 2 * (size_t)rel * n,
                      rel ? W1 : W0, Y + (size_t)rel * n * 64, n, blockIdx.x);
}

// ---------------- CSR pull aggregation (fp16 payload, fp32 accum, MLP=4) -----
__device__ __forceinline__ float2 csr_sum(const int* __restrict__ off,
                                          const int* __restrict__ csr,
                                          const __half2* __restrict__ ylane, int node) {
    int j = off[node], end = off[node + 1];
    float2 a0 = make_float2(0.f, 0.f), a1 = make_float2(0.f, 0.f);
    float2 a2 = make_float2(0.f, 0.f), a3 = make_float2(0.f, 0.f);
    for (; j + 4 <= end; j += 4) {
        int s0 = __ldg(csr + j + 0);
        int s1 = __ldg(csr + j + 1);
        int s2 = __ldg(csr + j + 2);
        int s3 = __ldg(csr + j + 3);
        __half2 h0 = __ldg(ylane + (size_t)s0 * 32);
        __half2 h1 = __ldg(ylane + (size_t)s1 * 32);
        __half2 h2 = __ldg(ylane + (size_t)s2 * 32);
        __half2 h3 = __ldg(ylane + (size_t)s3 * 32);
        float2 v0 = __half22float2(h0); a0.x += v0.x; a0.y += v0.y;
        float2 v1 = __half22float2(h1); a1.x += v1.x; a1.y += v1.y;
        float2 v2 = __half22float2(h2); a2.x += v2.x; a2.y += v2.y;
        float2 v3 = __half22float2(h3); a3.x += v3.x; a3.y += v3.y;
    }
    for (; j < end; j++) {
        int s = __ldg(csr + j);
        float2 v = __half22float2(__ldg(ylane + (size_t)s * 32));
        a0.x += v.x; a0.y += v.y;
    }
    a0.x += a1.x; a0.y += a1.y;
    a2.x += a3.x; a2.y += a3.y;
    a0.x += a2.x; a0.y += a2.y;
    return a0;
}

// layer 1: h_rel[i,:] = half(relu(c_dst[i] * sum y_rel[src] + b0_rel))
__global__ void agg_l1(const __half* __restrict__ y, const int* __restrict__ off,
                       const int* __restrict__ csr, const float* __restrict__ norms,
                       const float* __restrict__ b0p, const float* __restrict__ b0n,
                       __half* __restrict__ h, int n) {
    int rel = blockIdx.y;
    int node = blockIdx.x * 8 + (threadIdx.x >> 5);
    if (node >= n) return;
    int lane = threadIdx.x & 31;
    const __half2* yl = (const __half2*)(y + (size_t)rel * n * 64) + lane;
    float2 a = csr_sum(off + (size_t)rel * (n + 1), csr + (size_t)rel * EE, yl, node);
    float c = norms[(size_t)(1 + 2 * rel) * n + node];
    const float* b = rel ? b0n : b0p;
    float rx = fmaxf(c * a.x + b[2 * lane + 0], 0.f);
    float ry = fmaxf(c * a.y + b[2 * lane + 1], 0.f);
    ((__half2*)(h + (size_t)rel * n * 64 + (size_t)node * 64))[lane] =
        __floats2half2_rn(rx, ry);
}

// layer 2 fused: z = relu(cdp*sumP + b1p) - relu(cdn*sumN + b1n) + proj
__global__ void agg_l2(const __half* __restrict__ y, const int* __restrict__ off,
                       const int* __restrict__ csr, const float* __restrict__ norms,
                       const float* __restrict__ b1p, const float* __restrict__ b1n,
                       const float* __restrict__ Wc,
                       float* __restrict__ z, float* __restrict__ proj, int n) {
    int node = blockIdx.x * 8 + (threadIdx.x >> 5);
    if (node >= n) return;
    int lane = threadIdx.x & 31;
    const __half2* ylP = (const __half2*)y + lane;
    const __half2* ylN = (const __half2*)(y + (size_t)n * 64) + lane;
    float2 aP = csr_sum(off, csr, ylP, node);
    float2 aN = csr_sum(off + (n + 1), csr + (size_t)EE, ylN, node);
    float cp = norms[(size_t)n + node];
    float cn = norms[3 * (size_t)n + node];
    float2 r;
    r.x = fmaxf(cp * aP.x + b1p[2 * lane + 0], 0.f) - fmaxf(cn * aN.x + b1n[2 * lane + 0], 0.f);
    r.y = fmaxf(cp * aP.y + b1p[2 * lane + 1], 0.f) - fmaxf(cn * aN.y + b1n[2 * lane + 1], 0.f);
    *(float2*)(z + (size_t)node * 64 + lane * 2) = r;

    // classifier projections (Wc is [128][2] row-major)
    int k = 2 * lane;
    float s0 = r.x * __ldg(Wc + k * 2 + 0) + r.y * __ldg(Wc + (k + 1) * 2 + 0);
    float s1 = r.x * __ldg(Wc + k * 2 + 1) + r.y * __ldg(Wc + (k + 1) * 2 + 1);
    float d0 = r.x * __ldg(Wc + (128 + k * 2) + 0) + r.y * __ldg(Wc + (128 + (k + 1) * 2) + 0);
    float d1 = r.x * __ldg(Wc + (128 + k * 2) + 1) + r.y * __ldg(Wc + (128 + (k + 1) * 2) + 1);
    #pragma unroll
    for (int o = 16; o > 0; o >>= 1) {
        s0 += __shfl_xor_sync(0xffffffffu, s0, o);
        s1 += __shfl_xor_sync(0xffffffffu, s1, o);
        d0 += __shfl_xor_sync(0xffffffffu, d0, o);
        d1 += __shfl_xor_sync(0xffffffffu, d1, o);
    }
    if (lane == 0) ((float4*)proj)[node] = make_float4(s0, s1, d0, d1);
}

// ---------------- classifier: 2 x 16B per query ------------------------------
__global__ void cls_kernel(const float* __restrict__ p, const int* __restrict__ ei,
                           const float* __restrict__ bc, float* __restrict__ out, int nQ) {
    int q = blockIdx.x * blockDim.x + threadIdx.x;
    if (q >= nQ) return;
    int s = __ldg(ei + q);
    int d = __ldg(ei + nQ + q);
    float4 ps = ((const float4*)p)[s];
    float4 pd = ((const float4*)p)[d];
    float l0 = ps.x + pd.z + bc[0];
    float l1 = ps.y + pd.w + bc[1];
    float2 o;
    o.x = 1.f / (1.f + expf(-l0));
    o.y = 1.f / (1.f + expf(-l1));
    ((float2*)out)[q] = o;
}

// ---------------- launch -------------------------------------------------------
static inline int cdiv(long long a, int b) { return (int)((a + b - 1) / b); }

extern "C" void kernel_launch(void* const* d_in, const int* in_sizes, int n_in,
                              void* d_out, int out_size) {
    const float* x    = (const float*)d_in[0];
    const float* W0p  = (const float*)d_in[1];
    const float* b0p  = (const float*)d_in[2];
    const float* W0n  = (const float*)d_in[3];
    const float* b0n  = (const float*)d_in[4];
    const float* W1p  = (const float*)d_in[5];
    const float* b1p  = (const float*)d_in[6];
    const float* W1n  = (const float*)d_in[7];
    const float* b1n  = (const float*)d_in[8];
    const float* Wc   = (const float*)d_in[9];
    const float* bc   = (const float*)d_in[10];
    const int*   srcp = (const int*)d_in[11];
    const int*   dstp = (const int*)d_in[12];
    const int*   srcn = (const int*)d_in[13];
    const int*   dstn = (const int*)d_in[14];
    const int*   ei   = (const int*)d_in[15];

    const int n   = in_sizes[0] / HH;
    const int nEp = in_sizes[11];
    const int nEn = in_sizes[13];
    const int nQ  = in_sizes[15] / 2;

    __half *y, *h;
    float *norms, *pbuf;
    int *cnt, *off, *cur, *csr, *bsum;
    cudaGetSymbolAddress((void**)&y,     g_y);
    cudaGetSymbolAddress((void**)&h,     g_h);
    cudaGetSymbolAddress((void**)&norms, g_norms);
    cudaGetSymbolAddress((void**)&cnt,   g_cnt);
    cudaGetSymbolAddress((void**)&off,   g_off);
    cudaGetSymbolAddress((void**)&cur,   g_cur);
    cudaGetSymbolAddress((void**)&csr,   g_csr);
    cudaGetSymbolAddress((void**)&bsum,  g_bsum);
    cudaGetSymbolAddress((void**)&pbuf,  g_proj);

    float* z     = (float*)d_out;
    float* probs = (float*)d_out + (size_t)n * HH;

    const int nb    = cdiv(n, 1024);
    const int gGemm = cdiv(n, 64);
    const int gScat = cdiv(nEp > nEn ? nEp : nEn, 256);
    const int gAgg  = cdiv(n, 8);

    // degrees + norms + scan
    zero_int4<<<cdiv(n, 256), 256>>>((int4*)cnt, n);
    deg4_kernel<<<dim3(cdiv(nEp, 256), 4), 256>>>(srcp, dstp, srcn, dstn, cnt, n, nEp);
    norm_kernel<<<cdiv(4 * n, 256), 256>>>(cnt, norms, 4 * n);
    scan_partial<<<dim3(nb, 2), 256>>>(cnt, bsum, n);
    scan_blocksums<<<2, 128>>>(bsum, off, n, nb, nEp, nEn);
    scan_final<<<dim3(nb, 2), 256>>>(cnt, bsum, off, cur, n);

    // layer-1 GEMM (both rels) overlapped with CSR scatter (both rels)
    gemm1_scatter<<<2 * gGemm + 2 * gScat, 256>>>(
        x, norms, W0p, W0n, y, srcp, dstp, srcn, dstn, cur, csr,
        n, nEp, nEn, gGemm, gScat);

    // layer-1 aggregation -> h (fp16)
    agg_l1<<<dim3(gAgg, 2), 256>>>(y, off, csr, norms, b0p, b0n, h, n);

    // layer-2 GEMM (fp16 input)
    gemm_l2<<<dim3(gGemm, 2), 256>>>(h, norms, W1p, W1n, y, n);

    // layer-2 aggregation + combine + classifier projection
    agg_l2<<<gAgg, 256>>>(y, off, csr, norms, b1p, b1n, Wc, z, pbuf, n);

    // classifier
    cls_kernel<<<cdiv(nQ, 256), 256>>>(pbuf, ei, bc, probs, nQ);
}